// round 15
// baseline (speedup 1.0000x reference)
#include <cuda_runtime.h>
#include <math_constants.h>
#include <cstdint>

#define BB 32
#define HH 12
#define LL 512
#define DD 768
#define HD 64
#define KSEL 255
#define KOUT 256

#define OUT_MASK_OFF ((size_t)BB * KOUT * DD)
#define OUT_TOME_OFF (OUT_MASK_OFF + (size_t)BB * KOUT)

// ---------------- scratch ----------------
__device__ float g_imp_part[BB * HH * 4 * LL];
__device__ float g_att[BB * LL];
__device__ int   g_idx[BB * KSEL];
__device__ float g_sent[BB * DD];
__device__ float g_q[BB * DD];
__device__ float g_kbias[BB * HH];
__device__ float g_wke[BB * HH * DD];
__device__ float g_w[BB * HH * LL];
__device__ float g_hv[BB * HH * DD];
__device__ float g_ctx[BB * DD];

// ---------------- chain 1: prologue ----------------
__global__ void k_prologue(const float* __restrict__ am, float* __restrict__ out) {
    const int t = threadIdx.x;
    const int b = blockIdx.x;
    const int gid = b * 512 + t;
    const int nthr = 64 * 512;

    for (int i = gid; i < BB * DD; i += nthr) g_sent[i] = 0.f;
    for (int i = gid; i < BB * HH * DD; i += nthr) g_hv[i] = 0.f;
    for (int i = gid; i < BB * KOUT; i += nthr) out[OUT_TOME_OFF + i] = 1.f;
    if (gid < BB) out[OUT_MASK_OFF + (size_t)gid * KOUT + KSEL] = 0.f;

    if (b < BB) {
        __shared__ float red[LL];
        const float amv = am[b * LL + t];
        red[t] = amv;
        __syncthreads();
        for (int s = 256; s > 0; s >>= 1) {
            if (t < s) red[t] = fmaxf(red[t], red[t + s]);
            __syncthreads();
        }
        const float m = red[0];
        __syncthreads();
        const float e = __expf(amv - m);
        red[t] = e;
        __syncthreads();
        for (int s = 256; s > 0; s >>= 1) {
            if (t < s) red[t] += red[t + s];
            __syncthreads();
        }
        g_att[b * LL + t] = e / red[0];
    }
}

// ---------------- chain 2: sentences += sum_{l chunk} att*hidden (grid 6,8,B x128)
__global__ void k_sentence(const float* __restrict__ hidden) {
    const int t  = threadIdx.x;
    const int dc = blockIdx.x;
    const int lc = blockIdx.y;
    const int b  = blockIdx.z;
    __shared__ float s_att[64];
    if (t < 64) s_att[t] = g_att[b * LL + lc * 64 + t];
    __syncthreads();

    const float* hp = hidden + ((size_t)b * LL + lc * 64) * DD + dc * 128 + t;
    float acc = 0.f;
#pragma unroll 16
    for (int l = 0; l < 64; l++) acc += s_att[l] * hp[(size_t)l * DD];
    atomicAdd(&g_sent[b * DD + dc * 128 + t], acc);
}

// ---------------- chain 3: q = sent @ Wq + bq, ALL batches share W reads
// grid (12 dchunks of 64, 4 bgroups of 8), 512 thr = 8 b x 64 d
__global__ void k_qproj_all(const float* __restrict__ Wq, const float* __restrict__ bq) {
    const int t  = threadIdx.x;
    const int dc = blockIdx.x;
    const int bg = blockIdx.y;
    __shared__ float s_sent[8][DD];   // 24 KB

    for (int i = t; i < 8 * DD; i += 512) {
        const int bl = i / DD, j = i % DD;
        s_sent[bl][j] = g_sent[(bg * 8 + bl) * DD + j];
    }
    __syncthreads();

    const int bl = t >> 6;
    const int d  = t & 63;
    const float* wp = Wq + dc * 64 + d;
    float acc = bq[dc * 64 + d];
#pragma unroll 8
    for (int j = 0; j < DD; j++)
        acc += s_sent[bl][j] * __ldg(wp + (size_t)j * DD);
    g_q[(bg * 8 + bl) * DD + dc * 64 + d] = acc;
}

// ---------------- chain 4 (PROFILED): wke + kbias, batched over b
// wke[b,h,j] = sum_d Wk[j, h*64+d] * q[b, h*64+d]
// grid (12 jc, 12 h, 4 bg), 512 thr = 8 b x 64 j
__global__ void k_wke_all(const float* __restrict__ Wk, const float* __restrict__ bk) {
    const int t  = threadIdx.x;
    const int jc = blockIdx.x;
    const int h  = blockIdx.y;
    const int bg = blockIdx.z;
    __shared__ float s_wk[64][65];    // padded: conflict-free column reads
    __shared__ float s_q[8][HD];

    for (int i = t; i < 64 * 64; i += 512) {
        const int jj = i >> 6, d = i & 63;
        s_wk[jj][d] = Wk[(size_t)(jc * 64 + jj) * DD + h * HD + d];
    }
    {
        const int bl = t >> 6, d = t & 63;
        s_q[bl][d] = g_q[(bg * 8 + bl) * DD + h * HD + d];
    }
    __syncthreads();

    const int bl = t >> 6;
    const int jj = t & 63;
    float acc = 0.f;
#pragma unroll
    for (int d = 0; d < HD; d++) acc += s_wk[jj][d] * s_q[bl][d];
    g_wke[((size_t)(bg * 8 + bl) * HH + h) * DD + jc * 64 + jj] = acc;

    if (jc == 0) {
        const int w = t >> 5, lane = t & 31;
        if (w < 8) {
            float kb = s_q[w][lane] * bk[h * HD + lane]
                     + s_q[w][lane + 32] * bk[h * HD + lane + 32];
#pragma unroll
            for (int off = 16; off; off >>= 1)
                kb += __shfl_down_sync(0xffffffffu, kb, off);
            if (lane == 0) g_kbias[(bg * 8 + w) * HH + h] = kb;
        }
    }
}

// ---------------- chain 5: logits  grid (32,B) x384 — proven R9 form
__global__ void k_logits(const float* __restrict__ hidden, const float* __restrict__ am) {
    const int t = threadIdx.x;
    const int b = blockIdx.y;
    const int l0 = blockIdx.x * 16;
    __shared__ float s_h[16 * DD];   // 48 KB
    __shared__ float skb[HH];

    {
        const float4* src = (const float4*)(hidden + ((size_t)b * LL + l0) * DD);
        float4* dst = (float4*)s_h;
#pragma unroll
        for (int i = t; i < 16 * DD / 4; i += 384) dst[i] = src[i];
    }
    if (t < HH) skb[t] = g_kbias[b * HH + t];

    const int h = t >> 5, lane = t & 31;
    float wk[24];
    {
        const float* wkp = g_wke + ((size_t)b * HH + h) * DD + lane;
#pragma unroll
        for (int j = 0; j < 24; j++) wk[j] = wkp[32 * j];
    }
    __syncthreads();

    float acc[16];
#pragma unroll
    for (int li = 0; li < 16; li++) {
        const float* hp = s_h + li * DD + lane;
        float a = 0.f;
#pragma unroll
        for (int j = 0; j < 24; j++) a += hp[32 * j] * wk[j];
        acc[li] = a;
    }
#pragma unroll
    for (int li = 0; li < 16; li++) {
        float a = acc[li];
#pragma unroll
        for (int off = 16; off; off >>= 1) a += __shfl_down_sync(0xffffffffu, a, off);
        if (lane == 0) {
            const int l = l0 + li;
            const float amv = am[b * LL + l];
            g_w[((size_t)b * HH + h) * LL + l] =
                (amv < -10.f) ? -CUDART_INF_F : (a + skb[h]) * 0.125f;
        }
    }
}

// ---------------- chain 6: softmax over l, in place. grid (B*H) x512
__global__ void k_softmax_w() {
    const int t = threadIdx.x;
    const int bh = blockIdx.x;
    __shared__ float red[LL];
    const float v = g_w[(size_t)bh * LL + t];
    red[t] = v;
    __syncthreads();
    for (int s = 256; s > 0; s >>= 1) {
        if (t < s) red[t] = fmaxf(red[t], red[t + s]);
        __syncthreads();
    }
    const float m = red[0];
    __syncthreads();
    const float e = __expf(v - m);
    red[t] = e;
    __syncthreads();
    for (int s = 256; s > 0; s >>= 1) {
        if (t < s) red[t] += red[t + s];
        __syncthreads();
    }
    g_w[(size_t)bh * LL + t] = e / red[0];
}

// ---------------- chain 7: hv += sum_{l chunk} w*hidden  (grid 6,8,B x128)
__global__ void k_hv(const float* __restrict__ hidden) {
    const int t  = threadIdx.x;
    const int dc = blockIdx.x;
    const int lc = blockIdx.y;
    const int b  = blockIdx.z;
    __shared__ float sw[HH * 64];
    for (int i = t; i < HH * 64; i += 128) {
        const int h = i >> 6, l = i & 63;
        sw[i] = g_w[((size_t)b * HH + h) * LL + lc * 64 + l];
    }
    __syncthreads();

    float acc[HH];
#pragma unroll
    for (int h = 0; h < HH; h++) acc[h] = 0.f;

    const float* hp = hidden + ((size_t)b * LL + lc * 64) * DD + dc * 128 + t;
#pragma unroll 4
    for (int l = 0; l < 64; l++) {
        const float hval = hp[(size_t)l * DD];
#pragma unroll
        for (int h = 0; h < HH; h++) acc[h] += sw[h * 64 + l] * hval;
    }
#pragma unroll
    for (int h = 0; h < HH; h++)
        atomicAdd(&g_hv[((size_t)b * HH + h) * DD + dc * 128 + t], acc[h]);
}

// ---------------- chain 8: ctx[b, h*64+d] = hv[b,h,:]·Wv[:, h*64+d] + bv
// grid (12 h, 4 bg), 512 thr = 8 b x 64 d; Wv tile staged once per 8 batches
__global__ void k_ctx_all(const float* __restrict__ Wv, const float* __restrict__ bv) {
    const int t  = threadIdx.x;
    const int h  = blockIdx.x;
    const int bg = blockIdx.y;
    __shared__ float s_wv[64][65];
    __shared__ float s_hv[8][64];

    const int bl = t >> 6;
    const int d  = t & 63;
    float acc = bv[h * HD + d];

    for (int jt = 0; jt < 12; jt++) {
        for (int i = t; i < 64 * 64; i += 512) {
            const int jj = i >> 6, dd = i & 63;
            s_wv[jj][dd] = Wv[(size_t)(jt * 64 + jj) * DD + h * HD + dd];
        }
        {
            const int b2 = t >> 6, jj = t & 63;
            s_hv[b2][jj] = g_hv[((size_t)(bg * 8 + b2) * HH + h) * DD + jt * 64 + jj];
        }
        __syncthreads();
#pragma unroll
        for (int jj = 0; jj < 64; jj++) acc += s_hv[bl][jj] * s_wv[jj][d];
        __syncthreads();
    }
    g_ctx[(bg * 8 + bl) * DD + h * HD + d] = acc;
}

// ---------------- chain 9: new_token = ctx @ Wo + bo (batched W reads)
// grid (12 dchunks, 4 bg), 512 thr = 8 b x 64 d
__global__ void k_newtok_all(const float* __restrict__ Wo, const float* __restrict__ bo,
                             float* __restrict__ out) {
    const int t  = threadIdx.x;
    const int dc = blockIdx.x;
    const int bg = blockIdx.y;
    __shared__ float s_ctx[8][DD];    // 24 KB

    for (int i = t; i < 8 * DD; i += 512) {
        const int bl = i / DD, j = i % DD;
        s_ctx[bl][j] = g_ctx[(bg * 8 + bl) * DD + j];
    }
    __syncthreads();

    const int bl = t >> 6;
    const int d  = t & 63;
    const float* wp = Wo + dc * 64 + d;
    float acc = bo[dc * 64 + d];
#pragma unroll 8
    for (int j = 0; j < DD; j++)
        acc += s_ctx[bl][j] * __ldg(wp + (size_t)j * DD);
    out[((size_t)(bg * 8 + bl) * KOUT + KSEL) * DD + dc * 64 + d] = acc;
}

// ---------------- branch 1: column-sum partials (402 MB) grid B*H*4 x256
__global__ void __launch_bounds__(256, 3)
k_reduce_scores(const float* __restrict__ scores, const float* __restrict__ am) {
    const int t   = threadIdx.x;
    const int blk = blockIdx.x;
    const int qc  = blk & 3;
    const int bh  = blk >> 2;
    const int b   = bh / HH;

    __shared__ float s_af[128];
    const int q0 = qc * 128;
    if (t < 128) {
        float amv = am[b * LL + q0 + t];
        s_af[t] = (amv > -10.f) ? 1.f : 0.f;
    }
    __syncthreads();

    const int tq  = t >> 7;
    const int col = t & 127;
    const float4* base =
        (const float4*)(scores + ((size_t)bh * LL + q0 + tq * 64) * LL) + col;
    const float* af = s_af + tq * 64;

    float4 a0 = make_float4(0.f, 0.f, 0.f, 0.f);
#pragma unroll 8
    for (int q = 0; q < 64; q++) {
        const float f = af[q];
        float4 v = __ldcs(base + (size_t)q * (LL / 4));
        a0.x += f * v.x; a0.y += f * v.y;
        a0.z += f * v.z; a0.w += f * v.w;
    }
    __shared__ float s_red[2][LL];
    s_red[tq][col * 4 + 0] = a0.x;
    s_red[tq][col * 4 + 1] = a0.y;
    s_red[tq][col * 4 + 2] = a0.z;
    s_red[tq][col * 4 + 3] = a0.w;
    __syncthreads();
    const int slot = bh * 4 + qc;
    for (int i = t; i < LL; i += 256)
        g_imp_part[(size_t)slot * LL + i] = s_red[0][i] + s_red[1][i];
}

// ---------------- branch 2: top-K  grid B x512
__global__ void k_topk(const float* __restrict__ am) {
    const int t = threadIdx.x;
    const int b = blockIdx.x;

    __shared__ float sv[LL];
    __shared__ int   ssc[LL];

    const float amv = am[b * LL + t];
    const float afl = (amv > -10.f) ? 1.f : 0.f;

    float imp = 0.f;
    const float* pp = g_imp_part + (size_t)(b * HH * 4) * LL + t;
#pragma unroll 8
    for (int s = 0; s < HH * 4; s++) imp += pp[(size_t)s * LL];

    float v = imp * afl * (1.0f / (HH * LL));
    if (t == 0) v = CUDART_INF_F;
    sv[t] = v;
    __syncthreads();

    int rank = 0;
#pragma unroll 8
    for (int j = 0; j < LL; j++) {
        float vj = sv[j];
        rank += (vj > v) || (vj == v && j < t);
    }
    const int sel = (rank < KSEL) ? 1 : 0;

    ssc[t] = sel;
    __syncthreads();
    for (int off = 1; off < LL; off <<= 1) {
        int y = (t >= off) ? ssc[t - off] : 0;
        __syncthreads();
        ssc[t] += y;
        __syncthreads();
    }
    if (sel) g_idx[b * KSEL + (ssc[t] - 1)] = t;
}

// ---------------- branch 3: gather  grid (KSEL,B) x192
__global__ void k_gather(const float* __restrict__ hidden, const float* __restrict__ am,
                         float* __restrict__ out) {
    const int t = threadIdx.x;
    const int k = blockIdx.x;
    const int b = blockIdx.y;
    const int idx = g_idx[b * KSEL + k];
    const float4* src = (const float4*)(hidden + ((size_t)b * LL + idx) * DD);
    float4* dst = (float4*)(out + ((size_t)b * KOUT + k) * DD);
    dst[t] = src[t];
    if (t == 0) {
        out[OUT_MASK_OFF + (size_t)b * KOUT + k] = am[b * LL + idx];
    }
}

// ---------------- launcher ----------------
extern "C" void kernel_launch(void* const* d_in, const int* in_sizes, int n_in,
                              void* d_out, int out_size) {
    const float* hidden = (const float*)d_in[0];
    const float* am     = (const float*)d_in[1];
    const float* scores = (const float*)d_in[2];
    const float* Wq     = (const float*)d_in[3];
    const float* bq     = (const float*)d_in[4];
    const float* Wk     = (const float*)d_in[5];
    const float* bk     = (const float*)d_in[6];
    const float* Wv     = (const float*)d_in[7];
    const float* bv     = (const float*)d_in[8];
    const float* Wo     = (const float*)d_in[9];
    const float* bo     = (const float*)d_in[10];
    float* out = (float*)d_out;

    static cudaStream_t s2 = nullptr;
    static cudaEvent_t ev_fork = nullptr, ev_join = nullptr;
    if (s2 == nullptr) {
        cudaStreamCreateWithFlags(&s2, cudaStreamNonBlocking);
        cudaEventCreateWithFlags(&ev_fork, cudaEventDisableTiming);
        cudaEventCreateWithFlags(&ev_join, cudaEventDisableTiming);
    }

    k_prologue<<<64, 512>>>(am, out);                           // #1

    // FORK: branch depends on prologue only
    cudaEventRecord(ev_fork, 0);
    cudaStreamWaitEvent(s2, ev_fork, 0);

    // ----- chain (stream 0) -----
    {
        dim3 g(6, 8, BB);
        k_sentence<<<g, 128>>>(hidden);                         // #2
    }
    {
        dim3 g(12, 4);
        k_qproj_all<<<g, 512>>>(Wq, bq);                        // #3
    }
    {
        dim3 g(12, HH, 4);
        k_wke_all<<<g, 512>>>(Wk, bk);                          // #4 (profiled)
    }
    {
        dim3 g(32, BB);
        k_logits<<<g, 384>>>(hidden, am);                       // #5
    }
    k_softmax_w<<<BB * HH, 512>>>();                            // #6
    {
        dim3 g(6, 8, BB);
        k_hv<<<g, 128>>>(hidden);                               // #7
    }
    {
        dim3 g(HH, 4);
        k_ctx_all<<<g, 512>>>(Wv, bv);                          // #8
    }
    {
        dim3 g(12, 4);
        k_newtok_all<<<g, 512>>>(Wo, bo, out);                  // #9
    }

    // ----- branch (s2) -----
    k_reduce_scores<<<BB * HH * 4, 256, 0, s2>>>(scores, am);   // #10
    k_topk<<<BB, 512, 0, s2>>>(am);                             // #11
    {
        dim3 g(KSEL, BB);
        k_gather<<<g, 192, 0, s2>>>(hidden, am, out);           // #12
    }

    // JOIN
    cudaEventRecord(ev_join, s2);
    cudaStreamWaitEvent(0, ev_join, 0);
}

// round 16
// speedup vs baseline: 1.7491x; 1.7491x over previous
#include <cuda_runtime.h>
#include <math_constants.h>
#include <cstdint>

#define BB 32
#define HH 12
#define LL 512
#define DD 768
#define HD 64
#define KSEL 255
#define KOUT 256

#define OUT_MASK_OFF ((size_t)BB * KOUT * DD)
#define OUT_TOME_OFF (OUT_MASK_OFF + (size_t)BB * KOUT)

// ---------------- scratch ----------------
__device__ float g_imp_part[BB * HH * 4 * LL];
__device__ float g_att[BB * LL];
__device__ int   g_idx[BB * KSEL];
__device__ float g_sent[BB * DD];
__device__ float g_kbias[BB * HH];
__device__ float g_wke[BB * HH * DD];
__device__ float g_w[BB * HH * LL];
__device__ float g_hv[BB * HH * DD];
__device__ float g_ctx[BB * DD];

// ---------------- chain 1: init — zero accumulators + constant outputs
__global__ void k_init(float* __restrict__ out) {
    const int gid = blockIdx.x * blockDim.x + threadIdx.x;
    const int nthr = 64 * 512;
    for (int i = gid; i < BB * DD; i += nthr) g_sent[i] = 0.f;
    for (int i = gid; i < BB * HH * DD; i += nthr) g_hv[i] = 0.f;
    for (int i = gid; i < BB * KOUT; i += nthr) out[OUT_TOME_OFF + i] = 1.f;
    if (gid < BB) out[OUT_MASK_OFF + (size_t)gid * KOUT + KSEL] = 0.f;
}

// ---------------- chain 2: att = softmax(am) per batch  (grid B x512)
__global__ void k_att(const float* __restrict__ am) {
    const int t = threadIdx.x;
    const int b = blockIdx.x;
    __shared__ float red[LL];
    const float amv = am[b * LL + t];
    red[t] = amv;
    __syncthreads();
    for (int s = 256; s > 0; s >>= 1) {
        if (t < s) red[t] = fmaxf(red[t], red[t + s]);
        __syncthreads();
    }
    const float m = red[0];
    __syncthreads();
    const float e = __expf(amv - m);
    red[t] = e;
    __syncthreads();
    for (int s = 256; s > 0; s >>= 1) {
        if (t < s) red[t] += red[t + s];
        __syncthreads();
    }
    g_att[b * LL + t] = e / red[0];
}

// ---------------- chain 3: sentences += sum_{l chunk} att*hidden (grid 6,8,B x128)
__global__ void k_sentence(const float* __restrict__ hidden) {
    const int t  = threadIdx.x;
    const int dc = blockIdx.x;
    const int lc = blockIdx.y;
    const int b  = blockIdx.z;
    __shared__ float s_att[64];
    if (t < 64) s_att[t] = g_att[b * LL + lc * 64 + t];
    __syncthreads();

    const float* hp = hidden + ((size_t)b * LL + lc * 64) * DD + dc * 128 + t;
    float acc = 0.f;
#pragma unroll 16
    for (int l = 0; l < 64; l++) acc += s_att[l] * hp[(size_t)l * DD];
    atomicAdd(&g_sent[b * DD + dc * 128 + t], acc);
}

// ---------------- chain 4 (PROFILED): fused q-projection + effective-key (grid (H,B) x512)
__global__ void k_qk(const float* __restrict__ Wq, const float* __restrict__ bq,
                     const float* __restrict__ Wk, const float* __restrict__ bk) {
    const int t = threadIdx.x;
    const int h = blockIdx.x;
    const int b = blockIdx.y;
    __shared__ float s_sent[DD];
    __shared__ float s_part[8][HD];
    __shared__ float s_qh[HD];

    for (int i = t; i < DD; i += 512) s_sent[i] = g_sent[b * DD + i];
    __syncthreads();

    const int jg = t >> 6;
    const int d  = t & 63;
    {
        float acc = 0.f;
        const float* wp = Wq + h * HD + d;
#pragma unroll 8
        for (int j = jg * 96; j < jg * 96 + 96; j++)
            acc += s_sent[j] * wp[(size_t)j * DD];
        s_part[jg][d] = acc;
    }
    __syncthreads();
    if (t < HD) {
        float q = bq[h * HD + t];
#pragma unroll
        for (int g = 0; g < 8; g++) q += s_part[g][t];
        s_qh[t] = q;
    }
    __syncthreads();

    if (t < 32) {
        float kb = s_qh[t] * bk[h * HD + t] + s_qh[t + 32] * bk[h * HD + t + 32];
#pragma unroll
        for (int off = 16; off; off >>= 1) kb += __shfl_down_sync(0xffffffffu, kb, off);
        if (t == 0) g_kbias[b * HH + h] = kb;
    }

    const int w = t >> 5, lane = t & 31;
    const float qa = s_qh[lane], qb = s_qh[lane + 32];
    for (int j = w * 48; j < w * 48 + 48; j++) {
        const float* wp = Wk + (size_t)j * DD + h * HD;
        float a = wp[lane] * qa + wp[lane + 32] * qb;
#pragma unroll
        for (int off = 16; off; off >>= 1) a += __shfl_down_sync(0xffffffffu, a, off);
        if (lane == 0) g_wke[((size_t)b * HH + h) * DD + j] = a;
    }
}

// ---------------- chain 5: logits  grid (64,B) x384 — 8 rows/block, 24 KB smem
__global__ void k_logits(const float* __restrict__ hidden, const float* __restrict__ am) {
    const int t = threadIdx.x;
    const int b = blockIdx.y;
    const int l0 = blockIdx.x * 8;
    __shared__ float s_h[8 * DD];    // 24 KB
    __shared__ float skb[HH];

    {
        const float4* src = (const float4*)(hidden + ((size_t)b * LL + l0) * DD);
        float4* dst = (float4*)s_h;
#pragma unroll
        for (int i = t; i < 8 * DD / 4; i += 384) dst[i] = src[i];
    }
    if (t < HH) skb[t] = g_kbias[b * HH + t];

    const int h = t >> 5, lane = t & 31;
    float wk[24];
    {
        const float* wkp = g_wke + ((size_t)b * HH + h) * DD + lane;
#pragma unroll
        for (int j = 0; j < 24; j++) wk[j] = wkp[32 * j];
    }
    __syncthreads();

    float acc[8];
#pragma unroll
    for (int li = 0; li < 8; li++) {
        const float* hp = s_h + li * DD + lane;
        float a = 0.f;
#pragma unroll
        for (int j = 0; j < 24; j++) a += hp[32 * j] * wk[j];
        acc[li] = a;
    }
#pragma unroll
    for (int li = 0; li < 8; li++) {
        float a = acc[li];
#pragma unroll
        for (int off = 16; off; off >>= 1) a += __shfl_down_sync(0xffffffffu, a, off);
        if (lane == 0) {
            const int l = l0 + li;
            const float amv = am[b * LL + l];
            g_w[((size_t)b * HH + h) * LL + l] =
                (amv < -10.f) ? -CUDART_INF_F : (a + skb[h]) * 0.125f;
        }
    }
}

// ---------------- chain 6: softmax over l, in place. grid (B*H) x512
__global__ void k_softmax_w() {
    const int t = threadIdx.x;
    const int bh = blockIdx.x;
    __shared__ float red[LL];
    const float v = g_w[(size_t)bh * LL + t];
    red[t] = v;
    __syncthreads();
    for (int s = 256; s > 0; s >>= 1) {
        if (t < s) red[t] = fmaxf(red[t], red[t + s]);
        __syncthreads();
    }
    const float m = red[0];
    __syncthreads();
    const float e = __expf(v - m);
    red[t] = e;
    __syncthreads();
    for (int s = 256; s > 0; s >>= 1) {
        if (t < s) red[t] += red[t + s];
        __syncthreads();
    }
    g_w[(size_t)bh * LL + t] = e / red[0];
}

// ---------------- chain 7: hv += sum_{l chunk} w*hidden  (grid 6,8,B x128)
__global__ void k_hv(const float* __restrict__ hidden) {
    const int t  = threadIdx.x;
    const int dc = blockIdx.x;
    const int lc = blockIdx.y;
    const int b  = blockIdx.z;
    __shared__ float sw[HH * 64];
    for (int i = t; i < HH * 64; i += 128) {
        const int h = i >> 6, l = i & 63;
        sw[i] = g_w[((size_t)b * HH + h) * LL + lc * 64 + l];
    }
    __syncthreads();

    float acc[HH];
#pragma unroll
    for (int h = 0; h < HH; h++) acc[h] = 0.f;

    const float* hp = hidden + ((size_t)b * LL + lc * 64) * DD + dc * 128 + t;
#pragma unroll 4
    for (int l = 0; l < 64; l++) {
        const float hval = hp[(size_t)l * DD];
#pragma unroll
        for (int h = 0; h < HH; h++) acc[h] += sw[h * 64 + l] * hval;
    }
#pragma unroll
    for (int h = 0; h < HH; h++)
        atomicAdd(&g_hv[((size_t)b * HH + h) * DD + dc * 128 + t], acc[h]);
}

// ---------------- chain 8: ctx = hv·Wv + bv  (grid (H,B) x512)
__global__ void k_ctx(const float* __restrict__ Wv, const float* __restrict__ bv) {
    const int t = threadIdx.x;
    const int h = blockIdx.x;
    const int b = blockIdx.y;
    __shared__ float sh[DD];
    __shared__ float s_part[8][HD];
    for (int i = t; i < DD; i += 512) sh[i] = g_hv[((size_t)b * HH + h) * DD + i];
    __syncthreads();

    const int jg = t >> 6;
    const int d  = t & 63;
    float acc = 0.f;
    const float* wp = Wv + h * HD + d;
#pragma unroll 8
    for (int j = jg * 96; j < jg * 96 + 96; j++)
        acc += sh[j] * wp[(size_t)j * DD];
    s_part[jg][d] = acc;
    __syncthreads();
    if (t < HD) {
        float c = bv[h * HD + t];
#pragma unroll
        for (int g = 0; g < 8; g++) c += s_part[g][t];
        g_ctx[b * DD + h * HD + t] = c;
    }
}

// ---------------- chain 9: new_token = ctx @ Wo + bo  (grid (6,B) x512)
__global__ void k_newtok(const float* __restrict__ Wo, const float* __restrict__ bo,
                         float* __restrict__ out) {
    const int t  = threadIdx.x;
    const int dc = blockIdx.x;
    const int b  = blockIdx.y;
    __shared__ float sc[DD];
    __shared__ float s_part[4][128];
    for (int i = t; i < DD; i += 512) sc[i] = g_ctx[b * DD + i];
    __syncthreads();

    const int jg = t >> 7;
    const int d  = t & 127;
    float acc = 0.f;
    const float* wp = Wo + dc * 128 + d;
#pragma unroll 8
    for (int j = jg * 192; j < jg * 192 + 192; j++)
        acc += sc[j] * wp[(size_t)j * DD];
    s_part[jg][d] = acc;
    __syncthreads();
    if (t < 128) {
        float o = bo[dc * 128 + t] + s_part[0][t] + s_part[1][t] + s_part[2][t] + s_part[3][t];
        out[((size_t)b * KOUT + KSEL) * DD + dc * 128 + t] = o;
    }
}

// ---------------- branch 1: column-sum partials (402 MB) grid B*H*4 x256
__global__ void k_reduce_scores(const float* __restrict__ scores,
                                const float* __restrict__ am) {
    const int t   = threadIdx.x;
    const int blk = blockIdx.x;
    const int qc  = blk & 3;
    const int bh  = blk >> 2;
    const int b   = bh / HH;

    __shared__ float s_af[128];
    const int q0 = qc * 128;
    if (t < 128) {
        float amv = am[b * LL + q0 + t];
        s_af[t] = (amv > -10.f) ? 1.f : 0.f;
    }
    __syncthreads();

    const int tq  = t >> 7;
    const int col = t & 127;
    const float4* base =
        (const float4*)(scores + ((size_t)bh * LL + q0 + tq * 64) * LL) + col;
    const float* af = s_af + tq * 64;

    float4 a0 = make_float4(0.f, 0.f, 0.f, 0.f);
#pragma unroll 8
    for (int q = 0; q < 64; q++) {
        const float f = af[q];
        float4 v = __ldcs(base + (size_t)q * (LL / 4));
        a0.x += f * v.x; a0.y += f * v.y;
        a0.z += f * v.z; a0.w += f * v.w;
    }
    __shared__ float s_red[2][LL];
    s_red[tq][col * 4 + 0] = a0.x;
    s_red[tq][col * 4 + 1] = a0.y;
    s_red[tq][col * 4 + 2] = a0.z;
    s_red[tq][col * 4 + 3] = a0.w;
    __syncthreads();
    const int slot = bh * 4 + qc;
    for (int i = t; i < LL; i += 256)
        g_imp_part[(size_t)slot * LL + i] = s_red[0][i] + s_red[1][i];
}

// ---------------- branch 2: top-K (sum partials + exact stable rank + scan) grid B x512
__global__ void k_topk(const float* __restrict__ am) {
    const int t = threadIdx.x;
    const int b = blockIdx.x;

    __shared__ float sv[LL];
    __shared__ int   ssc[LL];

    const float amv = am[b * LL + t];
    const float afl = (amv > -10.f) ? 1.f : 0.f;

    float imp = 0.f;
    const float* pp = g_imp_part + (size_t)(b * HH * 4) * LL + t;
#pragma unroll 8
    for (int s = 0; s < HH * 4; s++) imp += pp[(size_t)s * LL];

    float v = imp * afl * (1.0f / (HH * LL));
    if (t == 0) v = CUDART_INF_F;
    sv[t] = v;
    __syncthreads();

    int rank = 0;
#pragma unroll 8
    for (int j = 0; j < LL; j++) {
        float vj = sv[j];
        rank += (vj > v) || (vj == v && j < t);
    }
    const int sel = (rank < KSEL) ? 1 : 0;

    ssc[t] = sel;
    __syncthreads();
    for (int off = 1; off < LL; off <<= 1) {
        int y = (t >= off) ? ssc[t - off] : 0;
        __syncthreads();
        ssc[t] += y;
        __syncthreads();
    }
    if (sel) g_idx[b * KSEL + (ssc[t] - 1)] = t;
}

// ---------------- branch 3: gather  grid (KSEL,B) x192
__global__ void k_gather(const float* __restrict__ hidden, const float* __restrict__ am,
                         float* __restrict__ out) {
    const int t = threadIdx.x;
    const int k = blockIdx.x;
    const int b = blockIdx.y;
    const int idx = g_idx[b * KSEL + k];
    const float4* src = (const float4*)(hidden + ((size_t)b * LL + idx) * DD);
    float4* dst = (float4*)(out + ((size_t)b * KOUT + k) * DD);
    dst[t] = src[t];
    if (t == 0) {
        out[OUT_MASK_OFF + (size_t)b * KOUT + k] = am[b * LL + idx];
    }
}

// ---------------- launcher ----------------
extern "C" void kernel_launch(void* const* d_in, const int* in_sizes, int n_in,
                              void* d_out, int out_size) {
    const float* hidden = (const float*)d_in[0];
    const float* am     = (const float*)d_in[1];
    const float* scores = (const float*)d_in[2];
    const float* Wq     = (const float*)d_in[3];
    const float* bq     = (const float*)d_in[4];
    const float* Wk     = (const float*)d_in[5];
    const float* bk     = (const float*)d_in[6];
    const float* Wv     = (const float*)d_in[7];
    const float* bv     = (const float*)d_in[8];
    const float* Wo     = (const float*)d_in[9];
    const float* bo     = (const float*)d_in[10];
    float* out = (float*)d_out;

    static cudaStream_t s2 = nullptr;
    static cudaEvent_t ev_fork = nullptr, ev_join = nullptr;
    if (s2 == nullptr) {
        cudaStreamCreateWithFlags(&s2, cudaStreamNonBlocking);
        cudaEventCreateWithFlags(&ev_fork, cudaEventDisableTiming);
        cudaEventCreateWithFlags(&ev_join, cudaEventDisableTiming);
    }

    k_init<<<64, 512>>>(out);                                   // #1
    k_att<<<BB, 512>>>(am);                                     // #2

    // FORK: branch depends on init only (recorded before chain enqueue)
    cudaEventRecord(ev_fork, 0);
    cudaStreamWaitEvent(s2, ev_fork, 0);

    // ----- chain (stream 0) -----
    {
        dim3 g(6, 8, BB);
        k_sentence<<<g, 128>>>(hidden);                         // #3
    }
    {
        dim3 g(HH, BB);
        k_qk<<<g, 512>>>(Wq, bq, Wk, bk);                       // #4 (profiled)
    }
    {
        dim3 g(64, BB);
        k_logits<<<g, 384>>>(hidden, am);                       // #5
    }
    k_softmax_w<<<BB * HH, 512>>>();                            // #6
    {
        dim3 g(6, 8, BB);
        k_hv<<<g, 128>>>(hidden);                               // #7
    }
    {
        dim3 g(HH, BB);
        k_ctx<<<g, 512>>>(Wv, bv);                              // #8
    }
    {
        dim3 g(6, BB);
        k_newtok<<<g, 512>>>(Wo, bo, out);                      // #9
    }

    // ----- branch (s2) -----
    k_reduce_scores<<<BB * HH * 4, 256, 0, s2>>>(scores, am);   // #10
    k_topk<<<BB, 512, 0, s2>>>(am);                             // #11
    {
        dim3 g(KSEL, BB);
        k_gather<<<g, 192, 0, s2>>>(hidden, am, out);           // #12
    }

    // JOIN
    cudaEventRecord(ev_join, s2);
    cudaStreamWaitEvent(0, ev_join, 0);
}